// round 4
// baseline (speedup 1.0000x reference)
#include <cuda_runtime.h>
#include <cstdint>

#define NUM_NODE 150
#define ROWF 600            // floats per row
#define ROWB 2400           // bytes per row
#define DEPTH 2             // pipeline stages per warp
#define WPB 8               // warps per block
#define THREADS 256
#define SMEM_BUF_OFF 1024
#define SMEM_TOTAL (SMEM_BUF_OFF + WPB * DEPTH * ROWB)   // 1024 + 38400 = 39424 < 48KB

static __device__ __forceinline__ uint32_t smem_u32(const void* p) {
    uint32_t a;
    asm("{ .reg .u64 t; cvta.to.shared.u64 t, %1; cvt.u32.u64 %0, t; }" : "=r"(a) : "l"(p));
    return a;
}
static __device__ __forceinline__ void mbar_init(uint32_t a, uint32_t cnt) {
    asm volatile("mbarrier.init.shared.b64 [%0], %1;" :: "r"(a), "r"(cnt) : "memory");
}
static __device__ __forceinline__ void mbar_expect_tx(uint32_t a, uint32_t bytes) {
    asm volatile("mbarrier.arrive.expect_tx.shared.b64 _, [%0], %1;" :: "r"(a), "r"(bytes) : "memory");
}
static __device__ __forceinline__ void mbar_wait(uint32_t a, uint32_t parity) {
    asm volatile(
        "{\n\t.reg .pred P;\n\t"
        "WL_%=:\n\t"
        "mbarrier.try_wait.parity.acquire.cta.shared::cta.b64 P, [%0], %1, 0x989680;\n\t"
        "@P bra.uni WD_%=;\n\t"
        "bra.uni WL_%=;\n\t"
        "WD_%=:\n\t}"
        :: "r"(a), "r"(parity) : "memory");
}
static __device__ __forceinline__ void tma_g2s(uint32_t dst, const void* src,
                                               uint32_t bytes, uint32_t bar) {
    asm volatile(
        "cp.async.bulk.shared::cta.global.mbarrier::complete_tx::bytes [%0], [%1], %2, [%3];"
        :: "r"(dst), "l"(src), "r"(bytes), "r"(bar) : "memory");
}

__global__ __launch_bounds__(THREADS)
void obstacle_lane_tma(const float* __restrict__ lf,
                       const float2* __restrict__ obs_pos,
                       const int* __restrict__ mask,
                       float* __restrict__ out,
                       int M, int W)
{
    extern __shared__ char smem[];
    uint32_t sb = smem_u32(smem);
    int tid = threadIdx.x;
    int wid = tid >> 5, lane = tid & 31;

    // mbarriers: one per (warp, stage) at smem[0..WPB*DEPTH*8)
    if (tid < WPB * DEPTH) mbar_init(sb + tid * 8, 1);
    __syncthreads();

    int gw = blockIdx.x * WPB + wid;
    uint32_t bar = sb + (uint32_t)wid * DEPTH * 8;
    uint32_t bufa = sb + SMEM_BUF_OFF + (uint32_t)wid * DEPTH * ROWB;
    char* bufp = smem + SMEM_BUF_OFF + (size_t)wid * DEPTH * ROWB;

    // ---- prologue: fill the pipeline ----
    if (lane == 0) {
#pragma unroll
        for (int s = 0; s < DEPTH; s++) {
            long r = gw + (long)s * W;
            if (r < M) {
                mbar_expect_tx(bar + s * 8, ROWB);
                tma_g2s(bufa + s * ROWB, lf + r * ROWF, ROWB, bar + s * 8);
            }
        }
    }

    int i0 = 1 + lane;
    int i4 = min(i0 + 128, 148);

    int k = 0;
    for (long r = gw; r < M; r += W, k++) {
        int s = k & 1;                 // DEPTH = 2
        int parity = (k >> 1) & 1;

        // rep point (mask sorted -> cache-hot; overlaps with mbarrier wait)
        float2 rp = __ldg(obs_pos + __ldg(mask + r));

        mbar_wait(bar + s * 8, parity);

        const float2* nxy = (const float2*)(bufp + s * ROWB);   // nxy[2*i] = node i (x,y)
        const float4* nd  = (const float4*)(bufp + s * ROWB);   // nd[i] = node i full

        // ---- argmin scan over nodes 1..148 (5 rounds, clamped tail) ----
        float2 n0 = nxy[2 * i0];
        float2 n1 = nxy[2 * (i0 + 32)];
        float2 n2 = nxy[2 * (i0 + 64)];
        float2 n3 = nxy[2 * (i0 + 96)];
        float2 n4 = nxy[2 * i4];

#define DIST2(v) (((v).x - rp.x) * ((v).x - rp.x) + ((v).y - rp.y) * ((v).y - rp.y))
        float best = DIST2(n0); int bidx = i0;
        float d;
        d = DIST2(n1); if (d < best) { best = d; bidx = i0 + 32; }
        d = DIST2(n2); if (d < best) { best = d; bidx = i0 + 64; }
        d = DIST2(n3); if (d < best) { best = d; bidx = i0 + 96; }
        d = DIST2(n4); if (d < best) { best = d; bidx = i4; }
#undef DIST2

        // butterfly min, then first-occurrence index among minima
        float m = best;
#pragma unroll
        for (int off = 16; off > 0; off >>= 1)
            m = fminf(m, __shfl_xor_sync(0xffffffffu, m, off));
        unsigned cand = (best == m) ? (unsigned)bidx : 0x7fffffffu;
        int gi = (int)__reduce_min_sync(0xffffffffu, cand);

        // ---- epilogue: all lanes compute redundantly from smem (broadcast LDS) ----
        float4 mn = nd[gi];
        float4 pv = nd[gi - 1];
        float4 nx = nd[gi + 1];

        float dpx = pv.x - mn.x, dpy = pv.y - mn.y, dpz = pv.z - mn.z, dpw = pv.w - mn.w;
        float dnx = nx.x - mn.x, dny = nx.y - mn.y, dnz = nx.z - mn.z, dnw = nx.w - mn.w;
        float dist_prev = dpx*dpx + dpy*dpy + dpz*dpz + dpw*dpw;
        float dist_next = dnx*dnx + dny*dny + dnz*dnz + dnw*dnw;

        int before, after;
        float sx, sy, ex, ey;
        if (dist_next < dist_prev) {
            before = gi;     after = gi + 1;
            sx = mn.x; sy = mn.y; ex = nx.x; ey = nx.y;
        } else {
            before = gi - 1; after = gi;
            sx = pv.x; sy = pv.y; ex = mn.x; ey = mn.y;
        }

        float lvx = ex - sx, lvy = ey - sy;
        float mag = sqrtf(lvx * lvx + lvy * lvy);
        float ux = lvx / mag, uy = lvy / mag;
        float pm = (rp.x - sx) * ux + (rp.y - sy) * uy;

        // output layout: [proj_pt (M,2) | indices (M,2) | rep (M,2)] flattened f32
        if (lane == 0) {
            *reinterpret_cast<float2*>(out + 2 * r) = make_float2(sx + pm * ux, sy + pm * uy);
        } else if (lane == 1) {
            *reinterpret_cast<float2*>(out + 2L * M + 2 * r) =
                make_float2((float)before, (float)after);
        } else if (lane == 2) {
            *reinterpret_cast<float2*>(out + 4L * M + 2 * r) = make_float2(rp.x, rp.y);
        }

        // ---- refill this stage for row r + DEPTH*W ----
        __syncwarp();
        long rn = r + (long)DEPTH * W;
        if (lane == 0 && rn < M) {
            mbar_expect_tx(bar + s * 8, ROWB);
            tma_g2s(bufa + s * ROWB, lf + rn * ROWF, ROWB, bar + s * 8);
        }
    }
}

extern "C" void kernel_launch(void* const* d_in, const int* in_sizes, int n_in,
                              void* d_out, int out_size)
{
    const float*  lf      = (const float*)d_in[0];   // (M, 150, 4) f32
    const float2* obs_pos = (const float2*)d_in[1];  // (N, 2) f32
    const int*    mask    = (const int*)d_in[2];     // (M, 1) i32
    float* out = (float*)d_out;

    int M = in_sizes[0] / ROWF;

    // persistent-ish grid: 5 blocks/SM potential (39.4KB smem each), 148 SMs
    int blocks = 740;
    int maxBlocksForM = (M + WPB - 1) / WPB;   // at least 1 row per warp if M small
    if (blocks > maxBlocksForM) blocks = maxBlocksForM;
    int W = blocks * WPB;

    obstacle_lane_tma<<<blocks, THREADS, SMEM_TOTAL>>>(lf, obs_pos, mask, out, M, W);
}

// round 5
// speedup vs baseline: 1.1051x; 1.1051x over previous
#include <cuda_runtime.h>

#define NUM_NODE 150
#define FEAT 4
#define ROWF (NUM_NODE * FEAT)   // 600 floats per row

// streaming float2 load with 256B L2 prefetch (sequential row stream -> pure win)
static __device__ __forceinline__ float2 ldcs256(const float* p) {
    float2 v;
    asm volatile("ld.global.cs.L2::256B.v2.f32 {%0,%1}, [%2];"
                 : "=f"(v.x), "=f"(v.y) : "l"(p));
    return v;
}

__global__ __launch_bounds__(256)
void obstacle_lane_kernel(const float* __restrict__ lf,
                          const float2* __restrict__ obs_pos,
                          const int* __restrict__ mask,
                          float* __restrict__ out,
                          int M)
{
    int warp = (blockIdx.x * blockDim.x + threadIdx.x) >> 5;
    int lane = threadIdx.x & 31;

    int r0 = 2 * warp;
    if (r0 >= M) return;
    int r1 = r0 + 1;
    if (r1 >= M) r1 = r0;           // duplicate (benign: identical writes)

    const float* row0 = lf + (long)r0 * ROWF;
    const float* row1 = lf + (long)r1 * ROWF;

    // rep = obs_pos[mask[r]]  (mask is sorted -> heavy cache reuse)
    float2 rp0 = __ldg(obs_pos + __ldg(mask + r0));
    float2 rp1 = __ldg(obs_pos + __ldg(mask + r1));

    // node indices for this lane: 1+lane, 33+lane, 65+lane, 97+lane, min(129+lane,148)
    int i4 = min(129 + lane, 148);
    int o0 = 4 * (1 + lane);
    int o4 = 4 * i4;

    // ---- front-batched: 10 independent streaming loads in flight ----
    float2 a0 = ldcs256(row0 + o0);
    float2 a1 = ldcs256(row0 + o0 + 128);
    float2 a2 = ldcs256(row0 + o0 + 256);
    float2 a3 = ldcs256(row0 + o0 + 384);
    float2 a4 = ldcs256(row0 + o4);
    float2 b0 = ldcs256(row1 + o0);
    float2 b1 = ldcs256(row1 + o0 + 128);
    float2 b2 = ldcs256(row1 + o0 + 256);
    float2 b3 = ldcs256(row1 + o0 + 384);
    float2 b4 = ldcs256(row1 + o4);

    // ---- two interleaved argmin chains ----
    float best0, best1;
    int   bidx0, bidx1;
    {
        float dx, dy, d;
        dx = a0.x - rp0.x; dy = a0.y - rp0.y; best0 = dx*dx + dy*dy; bidx0 = 1 + lane;
        dx = b0.x - rp1.x; dy = b0.y - rp1.y; best1 = dx*dx + dy*dy; bidx1 = 1 + lane;

        dx = a1.x - rp0.x; dy = a1.y - rp0.y; d = dx*dx + dy*dy;
        if (d < best0) { best0 = d; bidx0 = 33 + lane; }
        dx = b1.x - rp1.x; dy = b1.y - rp1.y; d = dx*dx + dy*dy;
        if (d < best1) { best1 = d; bidx1 = 33 + lane; }

        dx = a2.x - rp0.x; dy = a2.y - rp0.y; d = dx*dx + dy*dy;
        if (d < best0) { best0 = d; bidx0 = 65 + lane; }
        dx = b2.x - rp1.x; dy = b2.y - rp1.y; d = dx*dx + dy*dy;
        if (d < best1) { best1 = d; bidx1 = 65 + lane; }

        dx = a3.x - rp0.x; dy = a3.y - rp0.y; d = dx*dx + dy*dy;
        if (d < best0) { best0 = d; bidx0 = 97 + lane; }
        dx = b3.x - rp1.x; dy = b3.y - rp1.y; d = dx*dx + dy*dy;
        if (d < best1) { best1 = d; bidx1 = 97 + lane; }

        dx = a4.x - rp0.x; dy = a4.y - rp0.y; d = dx*dx + dy*dy;
        if (d < best0) { best0 = d; bidx0 = i4; }
        dx = b4.x - rp1.x; dy = b4.y - rp1.y; d = dx*dx + dy*dy;
        if (d < best1) { best1 = d; bidx1 = i4; }
    }

    // ---- butterfly min (both rows overlapped), then min-index among minima ----
    float m0 = best0, m1 = best1;
#pragma unroll
    for (int off = 16; off > 0; off >>= 1) {
        m0 = fminf(m0, __shfl_xor_sync(0xffffffffu, m0, off));
        m1 = fminf(m1, __shfl_xor_sync(0xffffffffu, m1, off));
    }
    unsigned c0 = (best0 == m0) ? (unsigned)bidx0 : 0x7fffffffu;
    unsigned c1 = (best1 == m1) ? (unsigned)bidx1 : 0x7fffffffu;
    int gi0 = (int)__reduce_min_sync(0xffffffffu, c0);
    int gi1 = (int)__reduce_min_sync(0xffffffffu, c1);

    // ---- epilogues for both rows run concurrently on lanes 0 and 1 ----
    if (lane < 2) {
        int    r   = (lane == 0) ? r0  : r1;
        int    bi  = (lane == 0) ? gi0 : gi1;
        float2 rp  = (lane == 0) ? rp0 : rp1;
        const float* row = (lane == 0) ? row0 : row1;

        float4 mn = *reinterpret_cast<const float4*>(row + 4 * bi);
        float4 pv = *reinterpret_cast<const float4*>(row + 4 * (bi - 1));
        float4 nx = *reinterpret_cast<const float4*>(row + 4 * (bi + 1));

        float dpx = pv.x - mn.x, dpy = pv.y - mn.y, dpz = pv.z - mn.z, dpw = pv.w - mn.w;
        float dnx = nx.x - mn.x, dny = nx.y - mn.y, dnz = nx.z - mn.z, dnw = nx.w - mn.w;
        float dist_prev = dpx*dpx + dpy*dpy + dpz*dpz + dpw*dpw;
        float dist_next = dnx*dnx + dny*dny + dnz*dnz + dnw*dnw;

        int before, after;
        float sx, sy, ex, ey;
        if (dist_next < dist_prev) {
            before = bi;     after = bi + 1;
            sx = mn.x; sy = mn.y; ex = nx.x; ey = nx.y;
        } else {
            before = bi - 1; after = bi;
            sx = pv.x; sy = pv.y; ex = mn.x; ey = mn.y;
        }

        float lvx = ex - sx, lvy = ey - sy;
        float mag = sqrtf(lvx * lvx + lvy * lvy);
        float ux = lvx / mag, uy = lvy / mag;
        float pm = (rp.x - sx) * ux + (rp.y - sy) * uy;

        // output layout: [proj_pt (M,2) | indices (M,2) | rep (M,2)] flattened f32
        long o1 = 2L * M;
        long o2 = 4L * M;
        out[2 * r + 0]      = sx + pm * ux;
        out[2 * r + 1]      = sy + pm * uy;
        out[o1 + 2 * r + 0] = (float)before;
        out[o1 + 2 * r + 1] = (float)after;
        out[o2 + 2 * r + 0] = rp.x;
        out[o2 + 2 * r + 1] = rp.y;
    }
}

extern "C" void kernel_launch(void* const* d_in, const int* in_sizes, int n_in,
                              void* d_out, int out_size)
{
    const float*  lf      = (const float*)d_in[0];   // (M, 150, 4) f32
    const float2* obs_pos = (const float2*)d_in[1];  // (N, 2) f32
    const int*    mask    = (const int*)d_in[2];     // (M, 1) i32
    float* out = (float*)d_out;

    int M = in_sizes[0] / ROWF;

    const int threads = 256;               // 8 warps/block, 2 rows/warp = 16 rows/block
    int warps_needed = (M + 1) / 2;
    int blocks = (warps_needed + 7) / 8;
    obstacle_lane_kernel<<<blocks, threads>>>(lf, obs_pos, mask, out, M);
}

// round 6
// speedup vs baseline: 1.1081x; 1.0027x over previous
#include <cuda_runtime.h>

#define NUM_NODE 150
#define FEAT 4
#define ROWF (NUM_NODE * FEAT)   // 600 floats per row

// streaming float2 load with 256B L2 prefetch (sequential row stream)
static __device__ __forceinline__ float2 ldcs256(const float* p) {
    float2 v;
    asm volatile("ld.global.cs.L2::256B.v2.f32 {%0,%1}, [%2];"
                 : "=f"(v.x), "=f"(v.y) : "l"(p));
    return v;
}
// streaming store (evict-first in L2: steady writeback drain, less R/W turnaround)
static __device__ __forceinline__ void stcs2(float* p, float x, float y) {
    asm volatile("st.global.cs.v2.f32 [%0], {%1,%2};" :: "l"(p), "f"(x), "f"(y) : "memory");
}

__global__ __launch_bounds__(256)
void obstacle_lane_kernel(const float* __restrict__ lf,
                          const float2* __restrict__ obs_pos,
                          const int* __restrict__ mask,
                          float* __restrict__ out,
                          int M)
{
    int warp = (blockIdx.x * blockDim.x + threadIdx.x) >> 5;
    int lane = threadIdx.x & 31;

    int r0 = 2 * warp;
    if (r0 >= M) return;
    int r1 = r0 + 1;
    if (r1 >= M) r1 = r0;           // duplicate (benign: identical writes)

    const float* row0 = lf + (long)r0 * ROWF;
    const float* row1 = lf + (long)r1 * ROWF;

    // rep = obs_pos[mask[r]]  (mask is sorted -> heavy cache reuse)
    float2 rp0 = __ldg(obs_pos + __ldg(mask + r0));
    float2 rp1 = __ldg(obs_pos + __ldg(mask + r1));

    // node indices for this lane: 1+lane, 33+lane, 65+lane, 97+lane, min(129+lane,148)
    int i4 = min(129 + lane, 148);
    int o0 = 4 * (1 + lane);
    int o4 = 4 * i4;

    // ---- front-batched: 10 independent streaming loads in flight ----
    float2 a0 = ldcs256(row0 + o0);
    float2 a1 = ldcs256(row0 + o0 + 128);
    float2 a2 = ldcs256(row0 + o0 + 256);
    float2 a3 = ldcs256(row0 + o0 + 384);
    float2 a4 = ldcs256(row0 + o4);
    float2 b0 = ldcs256(row1 + o0);
    float2 b1 = ldcs256(row1 + o0 + 128);
    float2 b2 = ldcs256(row1 + o0 + 256);
    float2 b3 = ldcs256(row1 + o0 + 384);
    float2 b4 = ldcs256(row1 + o4);

    // ---- two interleaved argmin chains ----
    float best0, best1;
    int   bidx0, bidx1;
    {
        float dx, dy, d;
        dx = a0.x - rp0.x; dy = a0.y - rp0.y; best0 = dx*dx + dy*dy; bidx0 = 1 + lane;
        dx = b0.x - rp1.x; dy = b0.y - rp1.y; best1 = dx*dx + dy*dy; bidx1 = 1 + lane;

        dx = a1.x - rp0.x; dy = a1.y - rp0.y; d = dx*dx + dy*dy;
        if (d < best0) { best0 = d; bidx0 = 33 + lane; }
        dx = b1.x - rp1.x; dy = b1.y - rp1.y; d = dx*dx + dy*dy;
        if (d < best1) { best1 = d; bidx1 = 33 + lane; }

        dx = a2.x - rp0.x; dy = a2.y - rp0.y; d = dx*dx + dy*dy;
        if (d < best0) { best0 = d; bidx0 = 65 + lane; }
        dx = b2.x - rp1.x; dy = b2.y - rp1.y; d = dx*dx + dy*dy;
        if (d < best1) { best1 = d; bidx1 = 65 + lane; }

        dx = a3.x - rp0.x; dy = a3.y - rp0.y; d = dx*dx + dy*dy;
        if (d < best0) { best0 = d; bidx0 = 97 + lane; }
        dx = b3.x - rp1.x; dy = b3.y - rp1.y; d = dx*dx + dy*dy;
        if (d < best1) { best1 = d; bidx1 = 97 + lane; }

        dx = a4.x - rp0.x; dy = a4.y - rp0.y; d = dx*dx + dy*dy;
        if (d < best0) { best0 = d; bidx0 = i4; }
        dx = b4.x - rp1.x; dy = b4.y - rp1.y; d = dx*dx + dy*dy;
        if (d < best1) { best1 = d; bidx1 = i4; }
    }

    // ---- butterfly min (both rows overlapped), then min-index among minima ----
    float m0 = best0, m1 = best1;
#pragma unroll
    for (int off = 16; off > 0; off >>= 1) {
        m0 = fminf(m0, __shfl_xor_sync(0xffffffffu, m0, off));
        m1 = fminf(m1, __shfl_xor_sync(0xffffffffu, m1, off));
    }
    unsigned c0 = (best0 == m0) ? (unsigned)bidx0 : 0x7fffffffu;
    unsigned c1 = (best1 == m1) ? (unsigned)bidx1 : 0x7fffffffu;
    int gi0 = (int)__reduce_min_sync(0xffffffffu, c0);
    int gi1 = (int)__reduce_min_sync(0xffffffffu, c1);

    // ---- epilogues for both rows run concurrently on lanes 0 and 1 ----
    if (lane < 2) {
        int    r   = (lane == 0) ? r0  : r1;
        int    bi  = (lane == 0) ? gi0 : gi1;
        float2 rp  = (lane == 0) ? rp0 : rp1;
        const float* row = (lane == 0) ? row0 : row1;

        float4 mn = *reinterpret_cast<const float4*>(row + 4 * bi);
        float4 pv = *reinterpret_cast<const float4*>(row + 4 * (bi - 1));
        float4 nx = *reinterpret_cast<const float4*>(row + 4 * (bi + 1));

        float dpx = pv.x - mn.x, dpy = pv.y - mn.y, dpz = pv.z - mn.z, dpw = pv.w - mn.w;
        float dnx = nx.x - mn.x, dny = nx.y - mn.y, dnz = nx.z - mn.z, dnw = nx.w - mn.w;
        float dist_prev = dpx*dpx + dpy*dpy + dpz*dpz + dpw*dpw;
        float dist_next = dnx*dnx + dny*dny + dnz*dnz + dnw*dnw;

        int before, after;
        float sx, sy, ex, ey;
        if (dist_next < dist_prev) {
            before = bi;     after = bi + 1;
            sx = mn.x; sy = mn.y; ex = nx.x; ey = nx.y;
        } else {
            before = bi - 1; after = bi;
            sx = pv.x; sy = pv.y; ex = mn.x; ey = mn.y;
        }

        float lvx = ex - sx, lvy = ey - sy;
        float mag = sqrtf(lvx * lvx + lvy * lvy);
        float ux = lvx / mag, uy = lvy / mag;
        float pm = (rp.x - sx) * ux + (rp.y - sy) * uy;

        // output layout: [proj_pt (M,2) | indices (M,2) | rep (M,2)] flattened f32
        long o1 = 2L * M;
        long o2 = 4L * M;
        stcs2(out + 2 * r,      sx + pm * ux,  sy + pm * uy);
        stcs2(out + o1 + 2 * r, (float)before, (float)after);
        stcs2(out + o2 + 2 * r, rp.x,          rp.y);
    }
}

extern "C" void kernel_launch(void* const* d_in, const int* in_sizes, int n_in,
                              void* d_out, int out_size)
{
    const float*  lf      = (const float*)d_in[0];   // (M, 150, 4) f32
    const float2* obs_pos = (const float2*)d_in[1];  // (N, 2) f32
    const int*    mask    = (const int*)d_in[2];     // (M, 1) i32
    float* out = (float*)d_out;

    int M = in_sizes[0] / ROWF;

    const int threads = 256;               // 8 warps/block, 2 rows/warp = 16 rows/block
    int warps_needed = (M + 1) / 2;
    int blocks = (warps_needed + 7) / 8;
    obstacle_lane_kernel<<<blocks, threads>>>(lf, obs_pos, mask, out, M);
}